// round 1
// baseline (speedup 1.0000x reference)
#include <cuda_runtime.h>

// Problem constants
#define BATCH 512
#define DD 512
#define NITER 16

// Scratch (device globals — no allocation allowed)
__device__ float g_r[BATCH * DD];
__device__ float g_p[BATCH * DD];
__device__ float g_y[BATCH * DD];
__device__ float g_q[BATCH * DD];
__device__ float g_shift[BATCH];
__device__ float g_oscale[BATCH];
__device__ float g_rr[BATCH];

// ---------------------------------------------------------------------------
// Init: per-batch scalars, rhs = exp(0.5 B) x - mu ; r = p = rhs ; y = 0 ;
// rr = ||rhs||^2
// ---------------------------------------------------------------------------
__global__ __launch_bounds__(256) void init_kernel(const float* __restrict__ x,
                                                   const float* __restrict__ t,
                                                   const float* __restrict__ mu) {
    int b = blockIdx.x;
    int tid = threadIdx.x;
    float tv = t[b];
    // beta_integral: (BETA_MAX-BETA_MIN)/(2*T_MAX) t^2 + BETA_MIN t = 9.95 t^2 + 0.1 t
    float B = 9.95f * tv * tv + 0.1f * tv;
    float eh = expf(0.5f * B);
    float shift = expm1f(B);                 // exp(B) - 1, cancellation-safe
    float rescale = sqrtf(-expm1f(-B));      // sqrt(1 - exp(-B))
    if (tid == 0) {
        g_shift[b] = shift;
        g_oscale[b] = -(eh * rescale);
    }
    float acc = 0.0f;
    __shared__ float sred[256];
#pragma unroll
    for (int k = 0; k < 2; k++) {
        int i = tid + k * 256;
        float v = eh * x[b * DD + i] - mu[i];
        g_r[b * DD + i] = v;
        g_p[b * DD + i] = v;
        g_y[b * DD + i] = 0.0f;
        acc += v * v;
    }
    sred[tid] = acc;
    __syncthreads();
    for (int s = 128; s > 0; s >>= 1) {
        if (tid < s) sred[tid] += sred[tid + s];
        __syncthreads();
    }
    if (tid == 0) g_rr[b] = sred[0];
}

// ---------------------------------------------------------------------------
// GEMM: q[b][j] = sum_k p[b][k] * C[k][j] + shift[b] * p[b][j]
// Tile: 32 (M=batch rows) x 64 (N), K-step 32, 128 threads, 4x4 per thread.
// C is 1 MB -> lives in L2; everything fp32 FFMA.
// ---------------------------------------------------------------------------
__global__ __launch_bounds__(128) void gemm_shift_kernel(const float* __restrict__ Cmat) {
    __shared__ float sPT[32][36];  // [k][m], padded
    __shared__ float sC[32][64];   // [k][n]

    const int bm = blockIdx.y * 32;  // batch-row tile
    const int bn = blockIdx.x * 64;  // N tile
    const int tid = threadIdx.x;
    const int tx = tid & 15;   // 0..15 -> N (x4)
    const int ty = tid >> 4;   // 0..7  -> M (x4)

    float acc[4][4];
#pragma unroll
    for (int i = 0; i < 4; i++)
#pragma unroll
        for (int j = 0; j < 4; j++) acc[i][j] = 0.0f;

    for (int k0 = 0; k0 < DD; k0 += 32) {
        // Load P tile (32 rows x 32 k), store transposed into sPT[k][m]
#pragma unroll
        for (int l = 0; l < 2; l++) {
            int s = tid * 2 + l;      // 0..255 float4 slots
            int row = s >> 3;         // 0..31
            int kq = s & 7;           // 0..7
            float4 v = *(const float4*)&g_p[(bm + row) * DD + k0 + kq * 4];
            sPT[kq * 4 + 0][row] = v.x;
            sPT[kq * 4 + 1][row] = v.y;
            sPT[kq * 4 + 2][row] = v.z;
            sPT[kq * 4 + 3][row] = v.w;
        }
        // Load C tile (32 k-rows x 64 n-cols)
#pragma unroll
        for (int l = 0; l < 4; l++) {
            int s = tid + 128 * l;    // 0..511 float4 slots
            int row = s >> 4;         // 0..31
            int cq = s & 15;          // 0..15
            *(float4*)&sC[row][cq * 4] =
                *(const float4*)&Cmat[(k0 + row) * DD + bn + cq * 4];
        }
        __syncthreads();

#pragma unroll
        for (int kk = 0; kk < 32; kk++) {
            float4 a = *(const float4*)&sPT[kk][ty * 4];
            float4 c = *(const float4*)&sC[kk][tx * 4];
            float av[4] = {a.x, a.y, a.z, a.w};
            float cv[4] = {c.x, c.y, c.z, c.w};
#pragma unroll
            for (int i = 0; i < 4; i++)
#pragma unroll
                for (int j = 0; j < 4; j++) acc[i][j] += av[i] * cv[j];
        }
        __syncthreads();
    }

    // Epilogue: add shift[b] * p and write q
#pragma unroll
    for (int i = 0; i < 4; i++) {
        int row = bm + ty * 4 + i;
        float sh = g_shift[row];
#pragma unroll
        for (int j = 0; j < 4; j++) {
            int col = bn + tx * 4 + j;
            g_q[row * DD + col] = acc[i][j] + sh * g_p[row * DD + col];
        }
    }
}

// ---------------------------------------------------------------------------
// CG update (one block per batch row):
//   alpha = rr / (p.q) ; y += alpha p ; r -= alpha q
//   beta = rr_new / rr ; p = r + beta p ; rr = rr_new
// ---------------------------------------------------------------------------
__global__ __launch_bounds__(256) void cg_update_kernel() {
    int b = blockIdx.x;
    int tid = threadIdx.x;
    __shared__ float sred[256];
    __shared__ float sAB[2];

    int i0 = b * DD + tid;
    int i1 = i0 + 256;
    float p0 = g_p[i0], p1 = g_p[i1];
    float q0 = g_q[i0], q1 = g_q[i1];

    sred[tid] = p0 * q0 + p1 * q1;
    __syncthreads();
    for (int s = 128; s > 0; s >>= 1) {
        if (tid < s) sred[tid] += sred[tid + s];
        __syncthreads();
    }
    if (tid == 0) sAB[0] = g_rr[b] / fmaxf(sred[0], 1e-30f);
    __syncthreads();
    float alpha = sAB[0];

    g_y[i0] += alpha * p0;
    g_y[i1] += alpha * p1;
    float r0 = g_r[i0] - alpha * q0;
    float r1 = g_r[i1] - alpha * q1;
    g_r[i0] = r0;
    g_r[i1] = r1;

    sred[tid] = r0 * r0 + r1 * r1;
    __syncthreads();
    for (int s = 128; s > 0; s >>= 1) {
        if (tid < s) sred[tid] += sred[tid + s];
        __syncthreads();
    }
    if (tid == 0) {
        float rro = g_rr[b];
        float rrn = sred[0];
        sAB[1] = rrn / fmaxf(rro, 1e-30f);
        g_rr[b] = rrn;
    }
    __syncthreads();
    float beta = sAB[1];

    g_p[i0] = r0 + beta * p0;
    g_p[i1] = r1 + beta * p1;
}

// ---------------------------------------------------------------------------
// Final: out = -(exp(0.5 B) * sqrt(1 - exp(-B))) * y
// ---------------------------------------------------------------------------
__global__ __launch_bounds__(256) void final_kernel(float* __restrict__ out) {
    int b = blockIdx.x;
    int tid = threadIdx.x;
    float s = g_oscale[b];
    out[b * DD + tid] = s * g_y[b * DD + tid];
    out[b * DD + tid + 256] = s * g_y[b * DD + tid + 256];
}

// ---------------------------------------------------------------------------
extern "C" void kernel_launch(void* const* d_in, const int* in_sizes, int n_in,
                              void* d_out, int out_size) {
    // metadata order (setup_inputs dict order): x [512,512], t [512],
    // posterior_mean [512], posterior_cov [512,512]
    const float* x = (const float*)d_in[0];
    const float* t = (const float*)d_in[1];
    const float* mu = (const float*)d_in[2];
    const float* cov = (const float*)d_in[3];
    float* out = (float*)d_out;

    init_kernel<<<BATCH, 256>>>(x, t, mu);
    dim3 ggrid(DD / 64, BATCH / 32);  // (8, 16) = 128 blocks
    for (int it = 0; it < NITER; it++) {
        gemm_shift_kernel<<<ggrid, 128>>>(cov);
        cg_update_kernel<<<BATCH, 256>>>();
    }
    final_kernel<<<BATCH, 256>>>(out);
}

// round 2
// speedup vs baseline: 2.1809x; 2.1809x over previous
#include <cuda_runtime.h>

// Problem constants
#define BATCH 512
#define DD 512
#define NITER 10
#define SPLITK 2
#define KSLICE (DD / SPLITK)   // 256

// Scratch (device globals — no allocation allowed)
__device__ float g_r[BATCH * DD];
__device__ float g_p[BATCH * DD];
__device__ float g_y[BATCH * DD];
__device__ float g_qp[SPLITK][BATCH * DD];  // split-K partial q
__device__ float g_shift[BATCH];
__device__ float g_oscale[BATCH];
__device__ float g_rr[BATCH];

// ---------------------------------------------------------------------------
// Init: per-batch scalars, rhs = exp(0.5 B) x - mu ; r = p = rhs ; y = 0 ;
// rr = ||rhs||^2
// ---------------------------------------------------------------------------
__global__ __launch_bounds__(256) void init_kernel(const float* __restrict__ x,
                                                   const float* __restrict__ t,
                                                   const float* __restrict__ mu) {
    int b = blockIdx.x;
    int tid = threadIdx.x;
    float tv = t[b];
    // beta_integral: 9.95 t^2 + 0.1 t
    float B = 9.95f * tv * tv + 0.1f * tv;
    float eh = expf(0.5f * B);
    float shift = expm1f(B);                 // exp(B) - 1
    float rescale = sqrtf(-expm1f(-B));      // sqrt(1 - exp(-B))
    if (tid == 0) {
        g_shift[b] = shift;
        g_oscale[b] = -(eh * rescale);
    }
    float acc = 0.0f;
    __shared__ float sred[256];
#pragma unroll
    for (int k = 0; k < 2; k++) {
        int i = tid + k * 256;
        float v = eh * x[b * DD + i] - mu[i];
        g_r[b * DD + i] = v;
        g_p[b * DD + i] = v;
        g_y[b * DD + i] = 0.0f;
        acc += v * v;
    }
    sred[tid] = acc;
    __syncthreads();
    for (int s = 128; s > 0; s >>= 1) {
        if (tid < s) sred[tid] += sred[tid + s];
        __syncthreads();
    }
    if (tid == 0) g_rr[b] = sred[0];
}

// ---------------------------------------------------------------------------
// Split-K GEMM: qp[kz][b][j] = sum_{k in slice kz} p[b][k] * C[k][j]
// Tile: 32 (M) x 64 (N), K-step 32, 128 threads, 4x4 per thread.
// Grid: (8, 16, 2) = 256 blocks -> 2 blocks/SM.
// ---------------------------------------------------------------------------
__global__ __launch_bounds__(128) void gemm_splitk_kernel(const float* __restrict__ Cmat) {
    __shared__ float sPT[32][36];  // [k][m], padded
    __shared__ float sC[32][64];   // [k][n]

    const int bm = blockIdx.y * 32;        // batch-row tile
    const int bn = blockIdx.x * 64;        // N tile
    const int kz = blockIdx.z;             // K slice
    const int kbase = kz * KSLICE;
    const int tid = threadIdx.x;
    const int tx = tid & 15;   // N (x4)
    const int ty = tid >> 4;   // M (x4)

    float acc[4][4];
#pragma unroll
    for (int i = 0; i < 4; i++)
#pragma unroll
        for (int j = 0; j < 4; j++) acc[i][j] = 0.0f;

    for (int k0 = kbase; k0 < kbase + KSLICE; k0 += 32) {
        // Load P tile (32 rows x 32 k), transposed into sPT[k][m]
#pragma unroll
        for (int l = 0; l < 2; l++) {
            int s = tid * 2 + l;
            int row = s >> 3;
            int kq = s & 7;
            float4 v = *(const float4*)&g_p[(bm + row) * DD + k0 + kq * 4];
            sPT[kq * 4 + 0][row] = v.x;
            sPT[kq * 4 + 1][row] = v.y;
            sPT[kq * 4 + 2][row] = v.z;
            sPT[kq * 4 + 3][row] = v.w;
        }
        // Load C tile (32 k-rows x 64 n-cols)
#pragma unroll
        for (int l = 0; l < 4; l++) {
            int s = tid + 128 * l;
            int row = s >> 4;
            int cq = s & 15;
            *(float4*)&sC[row][cq * 4] =
                *(const float4*)&Cmat[(k0 + row) * DD + bn + cq * 4];
        }
        __syncthreads();

#pragma unroll
        for (int kk = 0; kk < 32; kk++) {
            float4 a = *(const float4*)&sPT[kk][ty * 4];
            float4 c = *(const float4*)&sC[kk][tx * 4];
            float av[4] = {a.x, a.y, a.z, a.w};
            float cv[4] = {c.x, c.y, c.z, c.w};
#pragma unroll
            for (int i = 0; i < 4; i++)
#pragma unroll
                for (int j = 0; j < 4; j++) acc[i][j] += av[i] * cv[j];
        }
        __syncthreads();
    }

    float* qp = g_qp[kz];
#pragma unroll
    for (int i = 0; i < 4; i++) {
        int row = bm + ty * 4 + i;
#pragma unroll
        for (int j = 0; j < 4; j++) {
            int col = bn + tx * 4 + j;
            qp[row * DD + col] = acc[i][j];
        }
    }
}

// ---------------------------------------------------------------------------
// CG update (one block per batch row):
//   q = qp0 + qp1 + shift*p
//   alpha = rr / (p.q) ; y += alpha p ; r -= alpha q
//   beta = rr_new / rr ; p = r + beta p ; rr = rr_new
// ---------------------------------------------------------------------------
__global__ __launch_bounds__(256) void cg_update_kernel() {
    int b = blockIdx.x;
    int tid = threadIdx.x;
    __shared__ float sred[256];
    __shared__ float sAB[2];

    float sh = g_shift[b];
    int i0 = b * DD + tid;
    int i1 = i0 + 256;
    float p0 = g_p[i0], p1 = g_p[i1];
    float q0 = g_qp[0][i0] + g_qp[1][i0] + sh * p0;
    float q1 = g_qp[0][i1] + g_qp[1][i1] + sh * p1;

    sred[tid] = p0 * q0 + p1 * q1;
    __syncthreads();
    for (int s = 128; s > 0; s >>= 1) {
        if (tid < s) sred[tid] += sred[tid + s];
        __syncthreads();
    }
    if (tid == 0) sAB[0] = g_rr[b] / fmaxf(sred[0], 1e-30f);
    __syncthreads();
    float alpha = sAB[0];

    g_y[i0] += alpha * p0;
    g_y[i1] += alpha * p1;
    float r0 = g_r[i0] - alpha * q0;
    float r1 = g_r[i1] - alpha * q1;
    g_r[i0] = r0;
    g_r[i1] = r1;

    sred[tid] = r0 * r0 + r1 * r1;
    __syncthreads();
    for (int s = 128; s > 0; s >>= 1) {
        if (tid < s) sred[tid] += sred[tid + s];
        __syncthreads();
    }
    if (tid == 0) {
        float rro = g_rr[b];
        float rrn = sred[0];
        sAB[1] = rrn / fmaxf(rro, 1e-30f);
        g_rr[b] = rrn;
    }
    __syncthreads();
    float beta = sAB[1];

    g_p[i0] = r0 + beta * p0;
    g_p[i1] = r1 + beta * p1;
}

// ---------------------------------------------------------------------------
// Final: out = -(exp(0.5 B) * sqrt(1 - exp(-B))) * y
// ---------------------------------------------------------------------------
__global__ __launch_bounds__(256) void final_kernel(float* __restrict__ out) {
    int b = blockIdx.x;
    int tid = threadIdx.x;
    float s = g_oscale[b];
    out[b * DD + tid] = s * g_y[b * DD + tid];
    out[b * DD + tid + 256] = s * g_y[b * DD + tid + 256];
}

// ---------------------------------------------------------------------------
extern "C" void kernel_launch(void* const* d_in, const int* in_sizes, int n_in,
                              void* d_out, int out_size) {
    const float* x = (const float*)d_in[0];
    const float* t = (const float*)d_in[1];
    const float* mu = (const float*)d_in[2];
    const float* cov = (const float*)d_in[3];
    float* out = (float*)d_out;

    init_kernel<<<BATCH, 256>>>(x, t, mu);
    dim3 ggrid(DD / 64, BATCH / 32, SPLITK);  // (8, 16, 2) = 256 blocks
    for (int it = 0; it < NITER; it++) {
        gemm_splitk_kernel<<<ggrid, 128>>>(cov);
        cg_update_kernel<<<BATCH, 256>>>();
    }
    final_kernel<<<BATCH, 256>>>(out);
}

// round 3
// speedup vs baseline: 3.5154x; 1.6119x over previous
#include <cuda_runtime.h>

// Problem constants
#define BATCH 512
#define DD 512
#define NITER 7
#define SPLITK 4
#define KSLICE (DD / SPLITK)   // 128

// Scratch (device globals — no allocation allowed)
__device__ float g_r[BATCH * DD];
__device__ float g_p[BATCH * DD];
__device__ float g_y[BATCH * DD];
__device__ float g_qp[SPLITK][BATCH * DD];  // split-K partial q
__device__ float g_shift[BATCH];
__device__ float g_oscale[BATCH];
__device__ float g_rr[BATCH];

// ---------------------------------------------------------------------------
// Init: per-batch scalars, rhs = exp(0.5 B) x - mu ; r = p = rhs ; y = 0 ;
// rr = ||rhs||^2
// ---------------------------------------------------------------------------
__global__ __launch_bounds__(256) void init_kernel(const float* __restrict__ x,
                                                   const float* __restrict__ t,
                                                   const float* __restrict__ mu) {
    int b = blockIdx.x;
    int tid = threadIdx.x;
    float tv = t[b];
    // beta_integral: 9.95 t^2 + 0.1 t
    float B = 9.95f * tv * tv + 0.1f * tv;
    float eh = expf(0.5f * B);
    float shift = expm1f(B);                 // exp(B) - 1
    float rescale = sqrtf(-expm1f(-B));      // sqrt(1 - exp(-B))
    if (tid == 0) {
        g_shift[b] = shift;
        g_oscale[b] = -(eh * rescale);
    }
    float acc = 0.0f;
    __shared__ float sred[256];
#pragma unroll
    for (int k = 0; k < 2; k++) {
        int i = tid + k * 256;
        float v = eh * x[b * DD + i] - mu[i];
        g_r[b * DD + i] = v;
        g_p[b * DD + i] = v;
        g_y[b * DD + i] = 0.0f;
        acc += v * v;
    }
    sred[tid] = acc;
    __syncthreads();
    for (int s = 128; s > 0; s >>= 1) {
        if (tid < s) sred[tid] += sred[tid + s];
        __syncthreads();
    }
    if (tid == 0) g_rr[b] = sred[0];
}

// ---------------------------------------------------------------------------
// Split-K GEMM: qp[kz][b][j] = sum_{k in slice kz} p[b][k] * C[k][j]
// Tile: 32 (M) x 64 (N), K-step 32, 128 threads, 4x4 per thread.
// Grid: (8, 16, 4) = 512 blocks -> ~3.5 blocks/SM.
// ---------------------------------------------------------------------------
__global__ __launch_bounds__(128) void gemm_splitk_kernel(const float* __restrict__ Cmat) {
    __shared__ float sPT[32][36];  // [k][m], padded
    __shared__ float sC[32][64];   // [k][n]

    const int bm = blockIdx.y * 32;        // batch-row tile
    const int bn = blockIdx.x * 64;        // N tile
    const int kz = blockIdx.z;             // K slice
    const int kbase = kz * KSLICE;
    const int tid = threadIdx.x;
    const int tx = tid & 15;   // N (x4)
    const int ty = tid >> 4;   // M (x4)

    float acc[4][4];
#pragma unroll
    for (int i = 0; i < 4; i++)
#pragma unroll
        for (int j = 0; j < 4; j++) acc[i][j] = 0.0f;

    for (int k0 = kbase; k0 < kbase + KSLICE; k0 += 32) {
        // Load P tile (32 rows x 32 k), transposed into sPT[k][m]
#pragma unroll
        for (int l = 0; l < 2; l++) {
            int s = tid * 2 + l;
            int row = s >> 3;
            int kq = s & 7;
            float4 v = *(const float4*)&g_p[(bm + row) * DD + k0 + kq * 4];
            sPT[kq * 4 + 0][row] = v.x;
            sPT[kq * 4 + 1][row] = v.y;
            sPT[kq * 4 + 2][row] = v.z;
            sPT[kq * 4 + 3][row] = v.w;
        }
        // Load C tile (32 k-rows x 64 n-cols)
#pragma unroll
        for (int l = 0; l < 4; l++) {
            int s = tid + 128 * l;
            int row = s >> 4;
            int cq = s & 15;
            *(float4*)&sC[row][cq * 4] =
                *(const float4*)&Cmat[(k0 + row) * DD + bn + cq * 4];
        }
        __syncthreads();

#pragma unroll
        for (int kk = 0; kk < 32; kk++) {
            float4 a = *(const float4*)&sPT[kk][ty * 4];
            float4 c = *(const float4*)&sC[kk][tx * 4];
            float av[4] = {a.x, a.y, a.z, a.w};
            float cv[4] = {c.x, c.y, c.z, c.w};
#pragma unroll
            for (int i = 0; i < 4; i++)
#pragma unroll
                for (int j = 0; j < 4; j++) acc[i][j] += av[i] * cv[j];
        }
        __syncthreads();
    }

    float* qp = g_qp[kz];
#pragma unroll
    for (int i = 0; i < 4; i++) {
        int row = bm + ty * 4 + i;
#pragma unroll
        for (int j = 0; j < 4; j++) {
            int col = bn + tx * 4 + j;
            qp[row * DD + col] = acc[i][j];
        }
    }
}

// ---------------------------------------------------------------------------
// CG update (one block per batch row):
//   q = sum_kz qp[kz] + shift*p
//   alpha = rr / (p.q) ; y += alpha p ; r -= alpha q
//   beta = rr_new / rr ; p = r + beta p ; rr = rr_new
// ---------------------------------------------------------------------------
__global__ __launch_bounds__(256) void cg_update_kernel() {
    int b = blockIdx.x;
    int tid = threadIdx.x;
    __shared__ float sred[256];
    __shared__ float sAB[2];

    float sh = g_shift[b];
    int i0 = b * DD + tid;
    int i1 = i0 + 256;
    float p0 = g_p[i0], p1 = g_p[i1];
    float q0 = (g_qp[0][i0] + g_qp[1][i0]) + (g_qp[2][i0] + g_qp[3][i0]) + sh * p0;
    float q1 = (g_qp[0][i1] + g_qp[1][i1]) + (g_qp[2][i1] + g_qp[3][i1]) + sh * p1;

    sred[tid] = p0 * q0 + p1 * q1;
    __syncthreads();
    for (int s = 128; s > 0; s >>= 1) {
        if (tid < s) sred[tid] += sred[tid + s];
        __syncthreads();
    }
    if (tid == 0) sAB[0] = g_rr[b] / fmaxf(sred[0], 1e-30f);
    __syncthreads();
    float alpha = sAB[0];

    g_y[i0] += alpha * p0;
    g_y[i1] += alpha * p1;
    float r0 = g_r[i0] - alpha * q0;
    float r1 = g_r[i1] - alpha * q1;
    g_r[i0] = r0;
    g_r[i1] = r1;

    sred[tid] = r0 * r0 + r1 * r1;
    __syncthreads();
    for (int s = 128; s > 0; s >>= 1) {
        if (tid < s) sred[tid] += sred[tid + s];
        __syncthreads();
    }
    if (tid == 0) {
        float rro = g_rr[b];
        float rrn = sred[0];
        sAB[1] = rrn / fmaxf(rro, 1e-30f);
        g_rr[b] = rrn;
    }
    __syncthreads();
    float beta = sAB[1];

    g_p[i0] = r0 + beta * p0;
    g_p[i1] = r1 + beta * p1;
}

// ---------------------------------------------------------------------------
// Final: out = -(exp(0.5 B) * sqrt(1 - exp(-B))) * y
// ---------------------------------------------------------------------------
__global__ __launch_bounds__(256) void final_kernel(float* __restrict__ out) {
    int b = blockIdx.x;
    int tid = threadIdx.x;
    float s = g_oscale[b];
    out[b * DD + tid] = s * g_y[b * DD + tid];
    out[b * DD + tid + 256] = s * g_y[b * DD + tid + 256];
}

// ---------------------------------------------------------------------------
extern "C" void kernel_launch(void* const* d_in, const int* in_sizes, int n_in,
                              void* d_out, int out_size) {
    const float* x = (const float*)d_in[0];
    const float* t = (const float*)d_in[1];
    const float* mu = (const float*)d_in[2];
    const float* cov = (const float*)d_in[3];
    float* out = (float*)d_out;

    init_kernel<<<BATCH, 256>>>(x, t, mu);
    dim3 ggrid(DD / 64, BATCH / 32, SPLITK);  // (8, 16, 4) = 512 blocks
    for (int it = 0; it < NITER; it++) {
        gemm_splitk_kernel<<<ggrid, 128>>>(cov);
        cg_update_kernel<<<BATCH, 256>>>();
    }
    final_kernel<<<BATCH, 256>>>(out);
}

// round 4
// speedup vs baseline: 3.6604x; 1.0412x over previous
#include <cuda_runtime.h>

// Problem constants
#define BATCH 512
#define DD 512
#define NITER 7
#define SPLITK 8
#define KSLICE (DD / SPLITK)   // 64

// Scratch (device globals — no allocation allowed)
__device__ float g_r[BATCH * DD];
__device__ float g_p[BATCH * DD];
__device__ float g_y[BATCH * DD];
__device__ float g_qp[SPLITK][BATCH * DD];  // split-K partial q
__device__ float g_shift[BATCH];
__device__ float g_oscale[BATCH];
__device__ float g_rr[BATCH];

// ---------------------------------------------------------------------------
// Init: per-batch scalars, rhs = exp(0.5 B) x - mu ; r = p = rhs ; y = 0 ;
// rr = ||rhs||^2
// ---------------------------------------------------------------------------
__global__ __launch_bounds__(256) void init_kernel(const float* __restrict__ x,
                                                   const float* __restrict__ t,
                                                   const float* __restrict__ mu) {
    int b = blockIdx.x;
    int tid = threadIdx.x;
    float tv = t[b];
    // beta_integral: 9.95 t^2 + 0.1 t
    float B = 9.95f * tv * tv + 0.1f * tv;
    float eh = expf(0.5f * B);
    float shift = expm1f(B);                 // exp(B) - 1
    float rescale = sqrtf(-expm1f(-B));      // sqrt(1 - exp(-B))
    if (tid == 0) {
        g_shift[b] = shift;
        g_oscale[b] = -(eh * rescale);
    }
    float acc = 0.0f;
    __shared__ float sred[256];
#pragma unroll
    for (int k = 0; k < 2; k++) {
        int i = tid + k * 256;
        float v = eh * x[b * DD + i] - mu[i];
        g_r[b * DD + i] = v;
        g_p[b * DD + i] = v;
        g_y[b * DD + i] = 0.0f;
        acc += v * v;
    }
    sred[tid] = acc;
    __syncthreads();
    for (int s = 128; s > 0; s >>= 1) {
        if (tid < s) sred[tid] += sred[tid + s];
        __syncthreads();
    }
    if (tid == 0) g_rr[b] = sred[0];
}

// ---------------------------------------------------------------------------
// Split-K GEMM: qp[kz][b][j] = sum_{k in slice kz} p[b][k] * C[k][j]
// Tile: 32 (M) x 64 (N), full K-slice (64) staged in smem, one barrier,
// then 64 unrolled FMA steps with zero barriers.
// Grid: (8, 16, 8) = 1024 blocks -> ~7 blocks/SM.
// ---------------------------------------------------------------------------
__global__ __launch_bounds__(128) void gemm_splitk_kernel(const float* __restrict__ Cmat) {
    __shared__ float sPT[KSLICE][36];      // [k][m], padded (9.2 KB)
    __shared__ float sC[KSLICE][64];       // [k][n]        (16 KB)

    const int bm = blockIdx.y * 32;        // batch-row tile
    const int bn = blockIdx.x * 64;        // N tile
    const int kbase = blockIdx.z * KSLICE; // K slice start
    const int tid = threadIdx.x;
    const int tx = tid & 15;   // N (x4)
    const int ty = tid >> 4;   // M (x4)

    // Load P tile (32 rows x 64 k), transposed into sPT[k][m]
    // 32*64/4 = 512 float4 slots, 128 threads -> 4 each
#pragma unroll
    for (int l = 0; l < 4; l++) {
        int s = tid * 4 + l;          // 0..511
        int row = s >> 4;             // 0..31
        int kq = s & 15;              // 0..15
        float4 v = *(const float4*)&g_p[(bm + row) * DD + kbase + kq * 4];
        sPT[kq * 4 + 0][row] = v.x;
        sPT[kq * 4 + 1][row] = v.y;
        sPT[kq * 4 + 2][row] = v.z;
        sPT[kq * 4 + 3][row] = v.w;
    }
    // Load C tile (64 k-rows x 64 n-cols): 1024 float4 slots -> 8 each
#pragma unroll
    for (int l = 0; l < 8; l++) {
        int s = tid + 128 * l;        // 0..1023
        int row = s >> 4;             // 0..63
        int cq = s & 15;              // 0..15
        *(float4*)&sC[row][cq * 4] =
            *(const float4*)&Cmat[(kbase + row) * DD + bn + cq * 4];
    }
    __syncthreads();

    float acc[4][4];
#pragma unroll
    for (int i = 0; i < 4; i++)
#pragma unroll
        for (int j = 0; j < 4; j++) acc[i][j] = 0.0f;

#pragma unroll
    for (int kk = 0; kk < KSLICE; kk++) {
        float4 a = *(const float4*)&sPT[kk][ty * 4];
        float4 c = *(const float4*)&sC[kk][tx * 4];
        float av[4] = {a.x, a.y, a.z, a.w};
        float cv[4] = {c.x, c.y, c.z, c.w};
#pragma unroll
        for (int i = 0; i < 4; i++)
#pragma unroll
            for (int j = 0; j < 4; j++) acc[i][j] += av[i] * cv[j];
    }

    float* qp = g_qp[blockIdx.z];
#pragma unroll
    for (int i = 0; i < 4; i++) {
        int row = bm + ty * 4 + i;
#pragma unroll
        for (int j = 0; j < 4; j++) {
            int col = bn + tx * 4 + j;
            qp[row * DD + col] = acc[i][j];
        }
    }
}

// ---------------------------------------------------------------------------
// CG update (one block per batch row):
//   q = sum_kz qp[kz] + shift*p
//   alpha = rr / (p.q) ; y += alpha p ; r -= alpha q
//   beta = rr_new / rr ; p = r + beta p ; rr = rr_new
// ---------------------------------------------------------------------------
__global__ __launch_bounds__(256) void cg_update_kernel() {
    int b = blockIdx.x;
    int tid = threadIdx.x;
    __shared__ float sred[256];
    __shared__ float sAB[2];

    float sh = g_shift[b];
    int i0 = b * DD + tid;
    int i1 = i0 + 256;
    float p0 = g_p[i0], p1 = g_p[i1];
    float q0 = sh * p0, q1 = sh * p1;
#pragma unroll
    for (int kz = 0; kz < SPLITK; kz++) {
        q0 += g_qp[kz][i0];
        q1 += g_qp[kz][i1];
    }

    sred[tid] = p0 * q0 + p1 * q1;
    __syncthreads();
    for (int s = 128; s > 0; s >>= 1) {
        if (tid < s) sred[tid] += sred[tid + s];
        __syncthreads();
    }
    if (tid == 0) sAB[0] = g_rr[b] / fmaxf(sred[0], 1e-30f);
    __syncthreads();
    float alpha = sAB[0];

    g_y[i0] += alpha * p0;
    g_y[i1] += alpha * p1;
    float r0 = g_r[i0] - alpha * q0;
    float r1 = g_r[i1] - alpha * q1;
    g_r[i0] = r0;
    g_r[i1] = r1;

    sred[tid] = r0 * r0 + r1 * r1;
    __syncthreads();
    for (int s = 128; s > 0; s >>= 1) {
        if (tid < s) sred[tid] += sred[tid + s];
        __syncthreads();
    }
    if (tid == 0) {
        float rro = g_rr[b];
        float rrn = sred[0];
        sAB[1] = rrn / fmaxf(rro, 1e-30f);
        g_rr[b] = rrn;
    }
    __syncthreads();
    float beta = sAB[1];

    g_p[i0] = r0 + beta * p0;
    g_p[i1] = r1 + beta * p1;
}

// ---------------------------------------------------------------------------
// Final: out = -(exp(0.5 B) * sqrt(1 - exp(-B))) * y
// ---------------------------------------------------------------------------
__global__ __launch_bounds__(256) void final_kernel(float* __restrict__ out) {
    int b = blockIdx.x;
    int tid = threadIdx.x;
    float s = g_oscale[b];
    out[b * DD + tid] = s * g_y[b * DD + tid];
    out[b * DD + tid + 256] = s * g_y[b * DD + tid + 256];
}

// ---------------------------------------------------------------------------
extern "C" void kernel_launch(void* const* d_in, const int* in_sizes, int n_in,
                              void* d_out, int out_size) {
    const float* x = (const float*)d_in[0];
    const float* t = (const float*)d_in[1];
    const float* mu = (const float*)d_in[2];
    const float* cov = (const float*)d_in[3];
    float* out = (float*)d_out;

    init_kernel<<<BATCH, 256>>>(x, t, mu);
    dim3 ggrid(DD / 64, BATCH / 32, SPLITK);  // (8, 16, 8) = 1024 blocks
    for (int it = 0; it < NITER; it++) {
        gemm_splitk_kernel<<<ggrid, 128>>>(cov);
        cg_update_kernel<<<BATCH, 256>>>();
    }
    final_kernel<<<BATCH, 256>>>(out);
}

// round 6
// speedup vs baseline: 3.8557x; 1.0534x over previous
#include <cuda_runtime.h>
#include <cuda_bf16.h>
#include <cstdint>

// Problem constants
#define BATCH 512
#define DD 512
#define NITER 8
#define SPLITK 2
#define KPER (DD / SPLITK)      // 256 per CTA
#define BK 64                   // k-chunk staged in smem
#define APITCH 72               // padded smem pitch (bank-conflict-free ldmatrix)

// ---------------------------------------------------------------------------
// Scratch (device globals — no allocation allowed)
// ---------------------------------------------------------------------------
__device__ float g_r[BATCH * DD];
__device__ float g_p[BATCH * DD];
__device__ float g_y[BATCH * DD];
__device__ float g_qp[SPLITK][BATCH * DD];
__device__ __nv_bfloat16 g_p_hi[BATCH * DD];
__device__ __nv_bfloat16 g_p_lo[BATCH * DD];
__device__ __nv_bfloat16 g_c_hi[DD * DD];
__device__ __nv_bfloat16 g_c_lo[DD * DD];
__device__ float g_shift[BATCH];
__device__ float g_oscale[BATCH];
__device__ float g_rr[BATCH];

// ---------------------------------------------------------------------------
// PTX helpers (sm_80-era instructions only — safe for plain sm_103 ptxas)
// ---------------------------------------------------------------------------
__device__ __forceinline__ uint32_t smem_u32(const void* p) {
    uint32_t a;
    asm("{ .reg .u64 t; cvta.to.shared.u64 t, %1; cvt.u32.u64 %0, t; }"
        : "=r"(a) : "l"(p));
    return a;
}

__device__ __forceinline__ void ldsm4(uint32_t* r, uint32_t addr) {
    asm volatile("ldmatrix.sync.aligned.m8n8.x4.shared.b16 {%0,%1,%2,%3}, [%4];"
                 : "=r"(r[0]), "=r"(r[1]), "=r"(r[2]), "=r"(r[3]) : "r"(addr));
}

__device__ __forceinline__ void mma_bf16(float* d, const uint32_t* a,
                                         uint32_t b0, uint32_t b1) {
    asm volatile(
        "mma.sync.aligned.m16n8k16.row.col.f32.bf16.bf16.f32 "
        "{%0,%1,%2,%3}, {%4,%5,%6,%7}, {%8,%9}, {%0,%1,%2,%3};"
        : "+f"(d[0]), "+f"(d[1]), "+f"(d[2]), "+f"(d[3])
        : "r"(a[0]), "r"(a[1]), "r"(a[2]), "r"(a[3]), "r"(b0), "r"(b1));
}

// ---------------------------------------------------------------------------
// Init: per-batch scalars, rhs = exp(0.5 B) x - mu ; r = p = rhs ; y = 0 ;
// rr = ||rhs||^2 ; p hi/lo bf16 split
// ---------------------------------------------------------------------------
__global__ __launch_bounds__(256) void init_kernel(const float* __restrict__ x,
                                                   const float* __restrict__ t,
                                                   const float* __restrict__ mu) {
    int b = blockIdx.x;
    int tid = threadIdx.x;
    float tv = t[b];
    float B = 9.95f * tv * tv + 0.1f * tv;
    float eh = expf(0.5f * B);
    float shift = expm1f(B);
    float rescale = sqrtf(-expm1f(-B));
    if (tid == 0) {
        g_shift[b] = shift;
        g_oscale[b] = -(eh * rescale);
    }
    float acc = 0.0f;
    __shared__ float sred[256];
#pragma unroll
    for (int k = 0; k < 2; k++) {
        int i = b * DD + tid + k * 256;
        float v = eh * x[i] - mu[tid + k * 256];
        g_r[i] = v;
        g_p[i] = v;
        g_y[i] = 0.0f;
        __nv_bfloat16 h = __float2bfloat16(v);
        g_p_hi[i] = h;
        g_p_lo[i] = __float2bfloat16(v - __bfloat162float(h));
        acc += v * v;
    }
    sred[tid] = acc;
    __syncthreads();
    for (int s = 128; s > 0; s >>= 1) {
        if (tid < s) sred[tid] += sred[tid + s];
        __syncthreads();
    }
    if (tid == 0) g_rr[b] = sred[0];
}

// ---------------------------------------------------------------------------
// Prep C: bf16 hi/lo split of posterior_cov (symmetric: row n == col n)
// ---------------------------------------------------------------------------
__global__ __launch_bounds__(256) void prep_c_kernel(const float* __restrict__ cov) {
    int i = blockIdx.x;
    int tid = threadIdx.x;
#pragma unroll
    for (int k = 0; k < 2; k++) {
        int idx = i * DD + tid + k * 256;
        float v = cov[idx];
        __nv_bfloat16 h = __float2bfloat16(v);
        g_c_hi[idx] = h;
        g_c_lo[idx] = __float2bfloat16(v - __bfloat162float(h));
    }
}

// ---------------------------------------------------------------------------
// mma.sync GEMM: qp[kz][m][n] = sum_{k in slice} p[m][k] * C[n][k]
//   (C symmetric, so C[n][k] == C[k][n]; B operand is row n, k-contiguous
//    which is exactly mma.sync .row.col's B layout via ldmatrix)
// 3-product hi/lo split: Ahi*Bhi + Ahi*Blo + Alo*Bhi, fp32 accum.
// Block 64x64, 4 warps (2x2), warp tile 32x32 (2 m16 x 4 n8 frags).
// Grid (8, 8, SPLITK) = 128 CTAs.
// ---------------------------------------------------------------------------
__global__ __launch_bounds__(128) void gemm_mma_kernel() {
    __shared__ __nv_bfloat16 sAhi[64][APITCH];
    __shared__ __nv_bfloat16 sAlo[64][APITCH];
    __shared__ __nv_bfloat16 sBhi[64][APITCH];
    __shared__ __nv_bfloat16 sBlo[64][APITCH];

    const int tid = threadIdx.x;
    const int lid = tid & 31;
    const int wid = tid >> 5;
    const int wm = (wid & 1) * 32;   // warp m offset in tile
    const int wn = (wid >> 1) * 32;  // warp n offset in tile
    const int bm = blockIdx.y * 64;
    const int bn = blockIdx.x * 64;
    const int kbase = blockIdx.z * KPER;

    float acc[2][4][4];  // [m16 tile][n8 tile][frag]
#pragma unroll
    for (int i = 0; i < 2; i++)
#pragma unroll
        for (int j = 0; j < 4; j++)
#pragma unroll
            for (int v = 0; v < 4; v++) acc[i][j][v] = 0.0f;

    const int lrow = lid & 15;          // ldmatrix row within 16
    const int lcol8 = (lid >> 4) * 8;   // ldmatrix 8-col half

    for (int kc = kbase; kc < kbase + KPER; kc += BK) {
        __syncthreads();
        // Stage 4 tiles of 64x64 bf16 (8 uint4 per row; 512 slots / 128 thr)
#pragma unroll
        for (int i = 0; i < 4; i++) {
            int slot = tid + 128 * i;
            int row = slot >> 3;
            int c8 = (slot & 7) * 8;
            *(uint4*)&sAhi[row][c8] = *(const uint4*)&g_p_hi[(bm + row) * DD + kc + c8];
            *(uint4*)&sAlo[row][c8] = *(const uint4*)&g_p_lo[(bm + row) * DD + kc + c8];
            *(uint4*)&sBhi[row][c8] = *(const uint4*)&g_c_hi[(bn + row) * DD + kc + c8];
            *(uint4*)&sBlo[row][c8] = *(const uint4*)&g_c_lo[(bn + row) * DD + kc + c8];
        }
        __syncthreads();

#pragma unroll
        for (int ks = 0; ks < BK / 16; ks++) {
            int kk = ks * 16 + lcol8;
            uint32_t ahi[2][4], alo[2][4], bhi[2][4], blo[2][4];
#pragma unroll
            for (int mi = 0; mi < 2; mi++) {
                ldsm4(ahi[mi], smem_u32(&sAhi[wm + mi * 16 + lrow][kk]));
                ldsm4(alo[mi], smem_u32(&sAlo[wm + mi * 16 + lrow][kk]));
            }
#pragma unroll
            for (int nh = 0; nh < 2; nh++) {
                ldsm4(bhi[nh], smem_u32(&sBhi[wn + nh * 16 + lrow][kk]));
                ldsm4(blo[nh], smem_u32(&sBlo[wn + nh * 16 + lrow][kk]));
            }
#pragma unroll
            for (int mi = 0; mi < 2; mi++)
#pragma unroll
                for (int ni = 0; ni < 4; ni++) {
                    int nh = ni >> 1, sb = ni & 1;
                    // b frag: {k0-7, k8-15} for this n8 = {r[sb], r[sb+2]}
                    mma_bf16(acc[mi][ni], ahi[mi], bhi[nh][sb], bhi[nh][sb + 2]);
                    mma_bf16(acc[mi][ni], ahi[mi], blo[nh][sb], blo[nh][sb + 2]);
                    mma_bf16(acc[mi][ni], alo[mi], bhi[nh][sb], bhi[nh][sb + 2]);
                }
        }
    }

    // Epilogue: d-frag layout m16n8: lane g=lid>>2, t=lid&3
    //   d0,d1 -> (g, 2t),(g,2t+1) ; d2,d3 -> (g+8, 2t),(g+8,2t+1)
    float* qp = g_qp[blockIdx.z];
    const int g = lid >> 2, tq = lid & 3;
#pragma unroll
    for (int mi = 0; mi < 2; mi++)
#pragma unroll
        for (int ni = 0; ni < 4; ni++) {
            int row = bm + wm + mi * 16 + g;
            int col = bn + wn + ni * 8 + tq * 2;
            *(float2*)&qp[row * DD + col] = make_float2(acc[mi][ni][0], acc[mi][ni][1]);
            *(float2*)&qp[(row + 8) * DD + col] = make_float2(acc[mi][ni][2], acc[mi][ni][3]);
        }
}

// ---------------------------------------------------------------------------
// CG update (one block per batch row):
//   q = qp0 + qp1 + shift*p ; alpha = rr/(p.q) ; y += alpha p ; r -= alpha q
//   beta = rr_new/rr ; p = r + beta p (+ bf16 split) ; rr = rr_new
// ---------------------------------------------------------------------------
__global__ __launch_bounds__(256) void cg_update_kernel() {
    int b = blockIdx.x;
    int tid = threadIdx.x;
    __shared__ float sred[256];
    __shared__ float sAB[2];

    float sh = g_shift[b];
    int i0 = b * DD + tid;
    int i1 = i0 + 256;
    float p0 = g_p[i0], p1 = g_p[i1];
    float q0 = g_qp[0][i0] + g_qp[1][i0] + sh * p0;
    float q1 = g_qp[0][i1] + g_qp[1][i1] + sh * p1;

    sred[tid] = p0 * q0 + p1 * q1;
    __syncthreads();
    for (int s = 128; s > 0; s >>= 1) {
        if (tid < s) sred[tid] += sred[tid + s];
        __syncthreads();
    }
    if (tid == 0) sAB[0] = g_rr[b] / fmaxf(sred[0], 1e-30f);
    __syncthreads();
    float alpha = sAB[0];

    g_y[i0] += alpha * p0;
    g_y[i1] += alpha * p1;
    float r0 = g_r[i0] - alpha * q0;
    float r1 = g_r[i1] - alpha * q1;
    g_r[i0] = r0;
    g_r[i1] = r1;

    sred[tid] = r0 * r0 + r1 * r1;
    __syncthreads();
    for (int s = 128; s > 0; s >>= 1) {
        if (tid < s) sred[tid] += sred[tid + s];
        __syncthreads();
    }
    if (tid == 0) {
        float rro = g_rr[b];
        float rrn = sred[0];
        sAB[1] = rrn / fmaxf(rro, 1e-30f);
        g_rr[b] = rrn;
    }
    __syncthreads();
    float beta = sAB[1];

    float pn0 = r0 + beta * p0;
    float pn1 = r1 + beta * p1;
    g_p[i0] = pn0;
    g_p[i1] = pn1;
    __nv_bfloat16 h0 = __float2bfloat16(pn0);
    __nv_bfloat16 h1 = __float2bfloat16(pn1);
    g_p_hi[i0] = h0;
    g_p_hi[i1] = h1;
    g_p_lo[i0] = __float2bfloat16(pn0 - __bfloat162float(h0));
    g_p_lo[i1] = __float2bfloat16(pn1 - __bfloat162float(h1));
}

// ---------------------------------------------------------------------------
// Final: out = -(exp(0.5 B) * sqrt(1 - exp(-B))) * y
// ---------------------------------------------------------------------------
__global__ __launch_bounds__(256) void final_kernel(float* __restrict__ out) {
    int b = blockIdx.x;
    int tid = threadIdx.x;
    float s = g_oscale[b];
    out[b * DD + tid] = s * g_y[b * DD + tid];
    out[b * DD + tid + 256] = s * g_y[b * DD + tid + 256];
}

// ---------------------------------------------------------------------------
extern "C" void kernel_launch(void* const* d_in, const int* in_sizes, int n_in,
                              void* d_out, int out_size) {
    const float* x = (const float*)d_in[0];
    const float* t = (const float*)d_in[1];
    const float* mu = (const float*)d_in[2];
    const float* cov = (const float*)d_in[3];
    float* out = (float*)d_out;

    init_kernel<<<BATCH, 256>>>(x, t, mu);
    prep_c_kernel<<<DD, 256>>>(cov);
    dim3 ggrid(DD / 64, BATCH / 64, SPLITK);  // (8, 8, 2) = 128 CTAs
    for (int it = 0; it < NITER; it++) {
        gemm_mma_kernel<<<ggrid, 128>>>();
        cg_update_kernel<<<BATCH, 256>>>();
    }
    final_kernel<<<BATCH, 256>>>(out);
}

// round 7
// speedup vs baseline: 4.5975x; 1.1924x over previous
#include <cuda_runtime.h>
#include <cuda_bf16.h>
#include <cstdint>

// Problem constants
#define BATCH 512
#define DD 512
#define NITER 7
#define SPLITK 2
#define KPER (DD / SPLITK)      // 256 per CTA
#define BK 64                   // k-chunk staged in smem
#define APITCH 72               // padded smem pitch (bank-conflict-free ldmatrix)

// ---------------------------------------------------------------------------
// Scratch (device globals — no allocation allowed)
// ---------------------------------------------------------------------------
__device__ float g_r[BATCH * DD];
__device__ float g_p[BATCH * DD];
__device__ float g_y[BATCH * DD];
__device__ float g_qp[SPLITK][BATCH * DD];
__device__ __nv_bfloat16 g_p_hi[BATCH * DD];
__device__ __nv_bfloat16 g_p_lo[BATCH * DD];
__device__ __nv_bfloat16 g_c_hi[DD * DD];
__device__ __nv_bfloat16 g_c_lo[DD * DD];
__device__ float g_shift[BATCH];
__device__ float g_oscale[BATCH];
__device__ float g_rr[BATCH];

// ---------------------------------------------------------------------------
// PTX helpers (sm_80-era instructions only — safe for plain sm_103 ptxas)
// ---------------------------------------------------------------------------
__device__ __forceinline__ uint32_t smem_u32(const void* p) {
    uint32_t a;
    asm("{ .reg .u64 t; cvta.to.shared.u64 t, %1; cvt.u32.u64 %0, t; }"
        : "=r"(a) : "l"(p));
    return a;
}

__device__ __forceinline__ void ldsm4(uint32_t* r, uint32_t addr) {
    asm volatile("ldmatrix.sync.aligned.m8n8.x4.shared.b16 {%0,%1,%2,%3}, [%4];"
                 : "=r"(r[0]), "=r"(r[1]), "=r"(r[2]), "=r"(r[3]) : "r"(addr));
}

__device__ __forceinline__ void mma_bf16(float* d, const uint32_t* a,
                                         uint32_t b0, uint32_t b1) {
    asm volatile(
        "mma.sync.aligned.m16n8k16.row.col.f32.bf16.bf16.f32 "
        "{%0,%1,%2,%3}, {%4,%5,%6,%7}, {%8,%9}, {%0,%1,%2,%3};"
        : "+f"(d[0]), "+f"(d[1]), "+f"(d[2]), "+f"(d[3])
        : "r"(a[0]), "r"(a[1]), "r"(a[2]), "r"(a[3]), "r"(b0), "r"(b1));
}

__device__ __forceinline__ float warp_sum(float v) {
#pragma unroll
    for (int m = 16; m > 0; m >>= 1)
        v += __shfl_xor_sync(0xFFFFFFFFu, v, m);
    return v;
}

// ---------------------------------------------------------------------------
// Init: per-batch scalars, rhs = exp(0.5 B) x - mu ; r = p = rhs ; y = 0 ;
// rr = ||rhs||^2 ; p hi/lo bf16 split
// ---------------------------------------------------------------------------
__global__ __launch_bounds__(256) void init_kernel(const float* __restrict__ x,
                                                   const float* __restrict__ t,
                                                   const float* __restrict__ mu) {
    int b = blockIdx.x;
    int tid = threadIdx.x;
    float tv = t[b];
    float B = 9.95f * tv * tv + 0.1f * tv;
    float eh = expf(0.5f * B);
    float shift = expm1f(B);
    float rescale = sqrtf(-expm1f(-B));
    if (tid == 0) {
        g_shift[b] = shift;
        g_oscale[b] = -(eh * rescale);
    }
    float acc = 0.0f;
    __shared__ float sred[256];
#pragma unroll
    for (int k = 0; k < 2; k++) {
        int i = b * DD + tid + k * 256;
        float v = eh * x[i] - mu[tid + k * 256];
        g_r[i] = v;
        g_p[i] = v;
        g_y[i] = 0.0f;
        __nv_bfloat16 h = __float2bfloat16(v);
        g_p_hi[i] = h;
        g_p_lo[i] = __float2bfloat16(v - __bfloat162float(h));
        acc += v * v;
    }
    sred[tid] = acc;
    __syncthreads();
    for (int s = 128; s > 0; s >>= 1) {
        if (tid < s) sred[tid] += sred[tid + s];
        __syncthreads();
    }
    if (tid == 0) g_rr[b] = sred[0];
}

// ---------------------------------------------------------------------------
// Prep C: bf16 hi/lo split of posterior_cov (symmetric: row n == col n)
// ---------------------------------------------------------------------------
__global__ __launch_bounds__(256) void prep_c_kernel(const float* __restrict__ cov) {
    int i = blockIdx.x;
    int tid = threadIdx.x;
#pragma unroll
    for (int k = 0; k < 2; k++) {
        int idx = i * DD + tid + k * 256;
        float v = cov[idx];
        __nv_bfloat16 h = __float2bfloat16(v);
        g_c_hi[idx] = h;
        g_c_lo[idx] = __float2bfloat16(v - __bfloat162float(h));
    }
}

// ---------------------------------------------------------------------------
// mma.sync GEMM: qp[kz][m][n] = sum_{k in slice} p[m][k] * C[n][k]
// (unchanged from R6 — validated)
// ---------------------------------------------------------------------------
__global__ __launch_bounds__(128) void gemm_mma_kernel() {
    __shared__ __nv_bfloat16 sAhi[64][APITCH];
    __shared__ __nv_bfloat16 sAlo[64][APITCH];
    __shared__ __nv_bfloat16 sBhi[64][APITCH];
    __shared__ __nv_bfloat16 sBlo[64][APITCH];

    const int tid = threadIdx.x;
    const int lid = tid & 31;
    const int wid = tid >> 5;
    const int wm = (wid & 1) * 32;
    const int wn = (wid >> 1) * 32;
    const int bm = blockIdx.y * 64;
    const int bn = blockIdx.x * 64;
    const int kbase = blockIdx.z * KPER;

    float acc[2][4][4];
#pragma unroll
    for (int i = 0; i < 2; i++)
#pragma unroll
        for (int j = 0; j < 4; j++)
#pragma unroll
            for (int v = 0; v < 4; v++) acc[i][j][v] = 0.0f;

    const int lrow = lid & 15;
    const int lcol8 = (lid >> 4) * 8;

    for (int kc = kbase; kc < kbase + KPER; kc += BK) {
        __syncthreads();
#pragma unroll
        for (int i = 0; i < 4; i++) {
            int slot = tid + 128 * i;
            int row = slot >> 3;
            int c8 = (slot & 7) * 8;
            *(uint4*)&sAhi[row][c8] = *(const uint4*)&g_p_hi[(bm + row) * DD + kc + c8];
            *(uint4*)&sAlo[row][c8] = *(const uint4*)&g_p_lo[(bm + row) * DD + kc + c8];
            *(uint4*)&sBhi[row][c8] = *(const uint4*)&g_c_hi[(bn + row) * DD + kc + c8];
            *(uint4*)&sBlo[row][c8] = *(const uint4*)&g_c_lo[(bn + row) * DD + kc + c8];
        }
        __syncthreads();

#pragma unroll
        for (int ks = 0; ks < BK / 16; ks++) {
            int kk = ks * 16 + lcol8;
            uint32_t ahi[2][4], alo[2][4], bhi[2][4], blo[2][4];
#pragma unroll
            for (int mi = 0; mi < 2; mi++) {
                ldsm4(ahi[mi], smem_u32(&sAhi[wm + mi * 16 + lrow][kk]));
                ldsm4(alo[mi], smem_u32(&sAlo[wm + mi * 16 + lrow][kk]));
            }
#pragma unroll
            for (int nh = 0; nh < 2; nh++) {
                ldsm4(bhi[nh], smem_u32(&sBhi[wn + nh * 16 + lrow][kk]));
                ldsm4(blo[nh], smem_u32(&sBlo[wn + nh * 16 + lrow][kk]));
            }
#pragma unroll
            for (int mi = 0; mi < 2; mi++)
#pragma unroll
                for (int ni = 0; ni < 4; ni++) {
                    int nh = ni >> 1, sb = ni & 1;
                    mma_bf16(acc[mi][ni], ahi[mi], bhi[nh][sb], bhi[nh][sb + 2]);
                    mma_bf16(acc[mi][ni], ahi[mi], blo[nh][sb], blo[nh][sb + 2]);
                    mma_bf16(acc[mi][ni], alo[mi], bhi[nh][sb], bhi[nh][sb + 2]);
                }
        }
    }

    float* qp = g_qp[blockIdx.z];
    const int g = lid >> 2, tq = lid & 3;
#pragma unroll
    for (int mi = 0; mi < 2; mi++)
#pragma unroll
        for (int ni = 0; ni < 4; ni++) {
            int row = bm + wm + mi * 16 + g;
            int col = bn + wn + ni * 8 + tq * 2;
            *(float2*)&qp[row * DD + col] = make_float2(acc[mi][ni][0], acc[mi][ni][1]);
            *(float2*)&qp[(row + 8) * DD + col] = make_float2(acc[mi][ni][2], acc[mi][ni][3]);
        }
}

// ---------------------------------------------------------------------------
// CG update, warp-per-row, zero barriers. 16 elems/lane, all float4.
// LAST=true: write out = oscale*(y + alpha*p) and skip everything else.
// ---------------------------------------------------------------------------
template <bool LAST>
__global__ __launch_bounds__(128) void cg_update_kernel(float* __restrict__ out) {
    const int lane = threadIdx.x & 31;
    const int b = blockIdx.x * 4 + (threadIdx.x >> 5);
    const float sh = g_shift[b];
    const int base = b * DD + lane * 4;

    float4 p[4], q[4], r[4];
#pragma unroll
    for (int i = 0; i < 4; i++) {
        int idx = base + i * 128;
        p[i] = *(const float4*)&g_p[idx];
        float4 q0 = *(const float4*)&g_qp[0][idx];
        float4 q1 = *(const float4*)&g_qp[1][idx];
        q[i].x = q0.x + q1.x + sh * p[i].x;
        q[i].y = q0.y + q1.y + sh * p[i].y;
        q[i].z = q0.z + q1.z + sh * p[i].z;
        q[i].w = q0.w + q1.w + sh * p[i].w;
        r[i] = *(const float4*)&g_r[idx];
    }

    float dot = 0.0f;
#pragma unroll
    for (int i = 0; i < 4; i++)
        dot += p[i].x * q[i].x + p[i].y * q[i].y + p[i].z * q[i].z + p[i].w * q[i].w;
    dot = warp_sum(dot);

    float rro = g_rr[b];
    float alpha = rro / fmaxf(dot, 1e-30f);

    if (LAST) {
        float os = g_oscale[b];
#pragma unroll
        for (int i = 0; i < 4; i++) {
            int idx = base + i * 128;
            float4 y = *(const float4*)&g_y[idx];
            float4 o;
            o.x = os * (y.x + alpha * p[i].x);
            o.y = os * (y.y + alpha * p[i].y);
            o.z = os * (y.z + alpha * p[i].z);
            o.w = os * (y.w + alpha * p[i].w);
            *(float4*)&out[idx] = o;
        }
        return;
    }

    float rr_new = 0.0f;
#pragma unroll
    for (int i = 0; i < 4; i++) {
        int idx = base + i * 128;
        float4 y = *(const float4*)&g_y[idx];
        y.x += alpha * p[i].x; y.y += alpha * p[i].y;
        y.z += alpha * p[i].z; y.w += alpha * p[i].w;
        *(float4*)&g_y[idx] = y;
        r[i].x -= alpha * q[i].x; r[i].y -= alpha * q[i].y;
        r[i].z -= alpha * q[i].z; r[i].w -= alpha * q[i].w;
        *(float4*)&g_r[idx] = r[i];
        rr_new += r[i].x * r[i].x + r[i].y * r[i].y +
                  r[i].z * r[i].z + r[i].w * r[i].w;
    }
    rr_new = warp_sum(rr_new);
    float beta = rr_new / fmaxf(rro, 1e-30f);
    if (lane == 0) g_rr[b] = rr_new;

#pragma unroll
    for (int i = 0; i < 4; i++) {
        int idx = base + i * 128;
        float4 pn;
        pn.x = r[i].x + beta * p[i].x;
        pn.y = r[i].y + beta * p[i].y;
        pn.z = r[i].z + beta * p[i].z;
        pn.w = r[i].w + beta * p[i].w;
        *(float4*)&g_p[idx] = pn;

        __nv_bfloat162 h01, h23, l01, l23;
        float h;
        h = __bfloat162float(__float2bfloat16(pn.x));
        h01.x = __float2bfloat16(pn.x); l01.x = __float2bfloat16(pn.x - h);
        h = __bfloat162float(__float2bfloat16(pn.y));
        h01.y = __float2bfloat16(pn.y); l01.y = __float2bfloat16(pn.y - h);
        h = __bfloat162float(__float2bfloat16(pn.z));
        h23.x = __float2bfloat16(pn.z); l23.x = __float2bfloat16(pn.z - h);
        h = __bfloat162float(__float2bfloat16(pn.w));
        h23.y = __float2bfloat16(pn.w); l23.y = __float2bfloat16(pn.w - h);
        *(__nv_bfloat162*)&g_p_hi[idx] = h01;
        *(__nv_bfloat162*)&g_p_hi[idx + 2] = h23;
        *(__nv_bfloat162*)&g_p_lo[idx] = l01;
        *(__nv_bfloat162*)&g_p_lo[idx + 2] = l23;
    }
}

// ---------------------------------------------------------------------------
extern "C" void kernel_launch(void* const* d_in, const int* in_sizes, int n_in,
                              void* d_out, int out_size) {
    const float* x = (const float*)d_in[0];
    const float* t = (const float*)d_in[1];
    const float* mu = (const float*)d_in[2];
    const float* cov = (const float*)d_in[3];
    float* out = (float*)d_out;

    init_kernel<<<BATCH, 256>>>(x, t, mu);
    prep_c_kernel<<<DD, 256>>>(cov);
    dim3 ggrid(DD / 64, BATCH / 64, SPLITK);  // (8, 8, 2) = 128 CTAs
    for (int it = 0; it < NITER - 1; it++) {
        gemm_mma_kernel<<<ggrid, 128>>>();
        cg_update_kernel<false><<<BATCH / 4, 128>>>(nullptr);
    }
    gemm_mma_kernel<<<ggrid, 128>>>();
    cg_update_kernel<true><<<BATCH / 4, 128>>>(out);
}